// round 1
// baseline (speedup 1.0000x reference)
#include <cuda_runtime.h>
#include <stdint.h>

#define N_NODES_MAX 50000
#define D 128

// Scratch (no allocation allowed in kernel_launch)
__device__ float g_deg[N_NODES_MAX];
__device__ float g_inv[N_NODES_MAX];
__device__ float g_XW[(size_t)N_NODES_MAX * D];

// ---------------------------------------------------------------------------
// 1) degree init (self loop => start at 1.0)
// ---------------------------------------------------------------------------
__global__ void k_init_deg(int n) {
    int i = blockIdx.x * blockDim.x + threadIdx.x;
    if (i < n) g_deg[i] = 1.0f;
}

// ---------------------------------------------------------------------------
// 2) degree histogram over edge_dst
// ---------------------------------------------------------------------------
__global__ void k_deg(const int* __restrict__ dst, int E) {
    int i = blockIdx.x * blockDim.x + threadIdx.x;
    if (i < E) atomicAdd(&g_deg[dst[i]], 1.0f);
}

// ---------------------------------------------------------------------------
// 3) inv_sqrt_deg
// ---------------------------------------------------------------------------
__global__ void k_rsqrt(int n) {
    int i = blockIdx.x * blockDim.x + threadIdx.x;
    if (i < n) g_inv[i] = rsqrtf(g_deg[i]);
}

// ---------------------------------------------------------------------------
// 4) GEMM: XW = X @ W  (K = N = 128), fused self-loop epilogue:
//      g_XW[r]  = XW[r]
//      out[r]   = XW[r] * inv[r]^2     (initializes poisoned d_out)
// Block tile: 64 rows x 128 cols. 256 threads, each computes 4 rows x 8 cols.
// W fully resident in smem (64 KB), X tile padded to avoid bank conflicts.
// ---------------------------------------------------------------------------
#define BM 64
#define XS_LD 132   // padded leading dim for X tile (keeps float4 alignment, 4-bank skew per row)

__global__ void k_gemm(const float* __restrict__ X, const float* __restrict__ W,
                       float* __restrict__ out, int n) {
    extern __shared__ float sm[];
    float* Ws = sm;                 // [128][128]
    float* Xs = sm + D * D;         // [BM][XS_LD]

    const int tid = threadIdx.x;
    const int row0 = blockIdx.x * BM;

    // load W (16384 floats = 4096 float4)
    {
        float4* dsm = (float4*)Ws;
        const float4* src = (const float4*)W;
        for (int i = tid; i < (D * D) / 4; i += blockDim.x) dsm[i] = src[i];
    }
    // load X tile (rows guarded)
    for (int i = tid; i < BM * (D / 4); i += blockDim.x) {
        int r = i / (D / 4);
        int c4 = (i % (D / 4)) * 4;
        float4 v = make_float4(0.f, 0.f, 0.f, 0.f);
        int gr = row0 + r;
        if (gr < n) v = *(const float4*)(X + (size_t)gr * D + c4);
        *(float4*)&Xs[r * XS_LD + c4] = v;
    }
    __syncthreads();

    const int tx = tid & 15;        // 16 column groups
    const int ty = tid >> 4;        // 16 row groups
    const int c0 = tx * 8;
    const int r0 = ty * 4;

    float acc[4][8];
#pragma unroll
    for (int i = 0; i < 4; i++)
#pragma unroll
        for (int j = 0; j < 8; j++) acc[i][j] = 0.f;

#pragma unroll 8
    for (int k = 0; k < D; k++) {
        float x0 = Xs[(r0 + 0) * XS_LD + k];
        float x1 = Xs[(r0 + 1) * XS_LD + k];
        float x2 = Xs[(r0 + 2) * XS_LD + k];
        float x3 = Xs[(r0 + 3) * XS_LD + k];
        float4 w0 = *(const float4*)&Ws[k * D + c0];
        float4 w1 = *(const float4*)&Ws[k * D + c0 + 4];
        const float wv[8] = {w0.x, w0.y, w0.z, w0.w, w1.x, w1.y, w1.z, w1.w};
#pragma unroll
        for (int j = 0; j < 8; j++) {
            acc[0][j] = fmaf(x0, wv[j], acc[0][j]);
            acc[1][j] = fmaf(x1, wv[j], acc[1][j]);
            acc[2][j] = fmaf(x2, wv[j], acc[2][j]);
            acc[3][j] = fmaf(x3, wv[j], acc[3][j]);
        }
    }

#pragma unroll
    for (int i = 0; i < 4; i++) {
        int r = row0 + r0 + i;
        if (r >= n) continue;
        float s = g_inv[r];
        s = s * s;
        float4 a = make_float4(acc[i][0], acc[i][1], acc[i][2], acc[i][3]);
        float4 b = make_float4(acc[i][4], acc[i][5], acc[i][6], acc[i][7]);
        *(float4*)&g_XW[(size_t)r * D + c0]     = a;
        *(float4*)&g_XW[(size_t)r * D + c0 + 4] = b;
        float4 oa = make_float4(a.x * s, a.y * s, a.z * s, a.w * s);
        float4 ob = make_float4(b.x * s, b.y * s, b.z * s, b.w * s);
        *(float4*)&out[(size_t)r * D + c0]     = oa;
        *(float4*)&out[(size_t)r * D + c0 + 4] = ob;
    }
}

// ---------------------------------------------------------------------------
// 5) edge scatter: one warp per edge.
//    out[dst] += XW[src] * (inv[src]*inv[dst])
//    Lane l handles columns [4l, 4l+4): one float4 gather + 4 atomicAdds.
// ---------------------------------------------------------------------------
__global__ void k_scatter(const int* __restrict__ src, const int* __restrict__ dst,
                          float* __restrict__ out, int E) {
    int warp = (int)((blockIdx.x * (size_t)blockDim.x + threadIdx.x) >> 5);
    int lane = threadIdx.x & 31;
    if (warp >= E) return;
    int s = __ldg(&src[warp]);
    int d = __ldg(&dst[warp]);
    float norm = g_inv[s] * g_inv[d];
    float4 v = *(const float4*)(g_XW + (size_t)s * D + lane * 4);
    float* o = out + (size_t)d * D + lane * 4;
    atomicAdd(o + 0, v.x * norm);
    atomicAdd(o + 1, v.y * norm);
    atomicAdd(o + 2, v.z * norm);
    atomicAdd(o + 3, v.w * norm);
}

// ---------------------------------------------------------------------------
extern "C" void kernel_launch(void* const* d_in, const int* in_sizes, int n_in,
                              void* d_out, int out_size) {
    const float* X = (const float*)d_in[0];
    const float* W = (const float*)d_in[1];
    const int* esrc = (const int*)d_in[2];
    const int* edst = (const int*)d_in[3];
    float* out = (float*)d_out;

    int n = in_sizes[0] / D;     // 50000
    int E = in_sizes[2];         // 800000

    // dynamic smem for GEMM: W (64KB) + padded X tile (BM*XS_LD*4 = 33792)
    static int smem_set = 0;
    int smem_bytes = D * D * sizeof(float) + BM * XS_LD * sizeof(float);
    if (!smem_set) {
        cudaFuncSetAttribute(k_gemm, cudaFuncAttributeMaxDynamicSharedMemorySize, smem_bytes);
        smem_set = 1;
    }

    k_init_deg<<<(n + 255) / 256, 256>>>(n);
    k_deg<<<(E + 255) / 256, 256>>>(edst, E);
    k_rsqrt<<<(n + 255) / 256, 256>>>(n);
    k_gemm<<<(n + BM - 1) / BM, 256, smem_bytes>>>(X, W, out, n);

    // one warp per edge: 8 warps per 256-thread block
    int warps_per_block = 256 / 32;
    int nblk = (E + warps_per_block - 1) / warps_per_block;
    k_scatter<<<nblk, 256>>>(esrc, edst, out, E);
}

// round 2
// speedup vs baseline: 1.3303x; 1.3303x over previous
#include <cuda_runtime.h>
#include <stdint.h>

#define N_NODES_MAX 50000
#define E_MAX 800000
#define D 128

// Scratch (__device__ globals; no allocation allowed)
__device__ int   g_cnt[N_NODES_MAX];      // in-degree (excl. self loop)
__device__ int   g_rowptr[N_NODES_MAX];   // CSR row start
__device__ int   g_woff[N_NODES_MAX];     // fill cursors
__device__ int   g_es[E_MAX];             // src indices sorted by dst
__device__ float g_inv[N_NODES_MAX];
__device__ float g_XW[(size_t)N_NODES_MAX * D];  // (X@W) * inv[row]  (pre-scaled)

// ---------------------------------------------------------------------------
// 1) zero the histogram
// ---------------------------------------------------------------------------
__global__ void k_zero(int n) {
    int i = blockIdx.x * blockDim.x + threadIdx.x;
    if (i < n) g_cnt[i] = 0;
}

// ---------------------------------------------------------------------------
// 2) in-degree histogram over edge_dst (int atomics)
// ---------------------------------------------------------------------------
__global__ void k_deg(const int* __restrict__ dst, int E) {
    int i = blockIdx.x * blockDim.x + threadIdx.x;
    if (i < E) atomicAdd(&g_cnt[dst[i]], 1);
}

// ---------------------------------------------------------------------------
// 3) single-block scan: rowptr = exclusive_prefix(cnt); woff = rowptr;
//    inv = rsqrt(cnt + 1)
// ---------------------------------------------------------------------------
#define SCAN_T 1024
__global__ void k_scan(int n) {
    __shared__ int part[SCAN_T];
    int tid = threadIdx.x;
    int chunk = (n + SCAN_T - 1) / SCAN_T;
    int s0 = tid * chunk;
    int s1 = min(s0 + chunk, n);

    int s = 0;
    for (int i = s0; i < s1; i++) s += g_cnt[i];
    part[tid] = s;
    __syncthreads();

    // Hillis-Steele inclusive scan over the 1024 partials
    for (int off = 1; off < SCAN_T; off <<= 1) {
        int v = part[tid];
        int add = (tid >= off) ? part[tid - off] : 0;
        __syncthreads();
        part[tid] = v + add;
        __syncthreads();
    }

    int run = (tid > 0) ? part[tid - 1] : 0;  // exclusive start of my chunk
    for (int i = s0; i < s1; i++) {
        int c = g_cnt[i];
        g_rowptr[i] = run;
        g_woff[i]   = run;
        run += c;
        g_inv[i] = rsqrtf((float)c + 1.0f);
    }
}

// ---------------------------------------------------------------------------
// 4) CSR fill: place each edge's src at its slot in the dst-sorted order
// ---------------------------------------------------------------------------
__global__ void k_fill(const int* __restrict__ src, const int* __restrict__ dst, int E) {
    int i = blockIdx.x * blockDim.x + threadIdx.x;
    if (i < E) {
        int d = dst[i];
        int pos = atomicAdd(&g_woff[d], 1);
        g_es[pos] = src[i];
    }
}

// ---------------------------------------------------------------------------
// 5) GEMM: g_XW[r] = (X @ W)[r] * inv[r]
//    Block tile 64x128, 256 threads, 4x8 register blocking, W in smem.
// ---------------------------------------------------------------------------
#define BM 64
#define XS_LD 132

__global__ void k_gemm(const float* __restrict__ X, const float* __restrict__ W, int n) {
    extern __shared__ float sm[];
    float* Ws = sm;                 // [128][128]
    float* Xs = sm + D * D;         // [BM][XS_LD]

    const int tid = threadIdx.x;
    const int row0 = blockIdx.x * BM;

    {
        float4* dsm = (float4*)Ws;
        const float4* srcp = (const float4*)W;
        for (int i = tid; i < (D * D) / 4; i += blockDim.x) dsm[i] = srcp[i];
    }
    for (int i = tid; i < BM * (D / 4); i += blockDim.x) {
        int r = i / (D / 4);
        int c4 = (i % (D / 4)) * 4;
        float4 v = make_float4(0.f, 0.f, 0.f, 0.f);
        int gr = row0 + r;
        if (gr < n) v = *(const float4*)(X + (size_t)gr * D + c4);
        *(float4*)&Xs[r * XS_LD + c4] = v;
    }
    __syncthreads();

    const int tx = tid & 15;
    const int ty = tid >> 4;
    const int c0 = tx * 8;
    const int r0 = ty * 4;

    float acc[4][8];
#pragma unroll
    for (int i = 0; i < 4; i++)
#pragma unroll
        for (int j = 0; j < 8; j++) acc[i][j] = 0.f;

#pragma unroll 8
    for (int k = 0; k < D; k++) {
        float x0 = Xs[(r0 + 0) * XS_LD + k];
        float x1 = Xs[(r0 + 1) * XS_LD + k];
        float x2 = Xs[(r0 + 2) * XS_LD + k];
        float x3 = Xs[(r0 + 3) * XS_LD + k];
        float4 w0 = *(const float4*)&Ws[k * D + c0];
        float4 w1 = *(const float4*)&Ws[k * D + c0 + 4];
        const float wv[8] = {w0.x, w0.y, w0.z, w0.w, w1.x, w1.y, w1.z, w1.w};
#pragma unroll
        for (int j = 0; j < 8; j++) {
            acc[0][j] = fmaf(x0, wv[j], acc[0][j]);
            acc[1][j] = fmaf(x1, wv[j], acc[1][j]);
            acc[2][j] = fmaf(x2, wv[j], acc[2][j]);
            acc[3][j] = fmaf(x3, wv[j], acc[3][j]);
        }
    }

#pragma unroll
    for (int i = 0; i < 4; i++) {
        int r = row0 + r0 + i;
        if (r >= n) continue;
        float s = g_inv[r];
        float4 a = make_float4(acc[i][0] * s, acc[i][1] * s, acc[i][2] * s, acc[i][3] * s);
        float4 b = make_float4(acc[i][4] * s, acc[i][5] * s, acc[i][6] * s, acc[i][7] * s);
        *(float4*)&g_XW[(size_t)r * D + c0]     = a;
        *(float4*)&g_XW[(size_t)r * D + c0 + 4] = b;
    }
}

// ---------------------------------------------------------------------------
// 6) aggregation: one warp per node, zero atomics.
//    out[i] = inv[i] * ( g_XW[i] + sum_{e in row(i)} g_XW[src_e] )
//    Lane l owns columns [4l, 4l+4) as a float4 register accumulator.
// ---------------------------------------------------------------------------
__global__ void k_agg(float* __restrict__ out, int n) {
    int node = (int)((blockIdx.x * (size_t)blockDim.x + threadIdx.x) >> 5);
    int lane = threadIdx.x & 31;
    if (node >= n) return;

    const float4* base = (const float4*)g_XW;
    int beg = g_rowptr[node];
    int cnt = g_cnt[node];

    float4 acc = base[(size_t)node * 32 + lane];  // self term (pre-scaled)

    int j = 0;
    for (; j + 1 < cnt; j += 2) {
        int s0 = g_es[beg + j];
        int s1 = g_es[beg + j + 1];
        float4 v0 = base[(size_t)s0 * 32 + lane];
        float4 v1 = base[(size_t)s1 * 32 + lane];
        acc.x += v0.x + v1.x;
        acc.y += v0.y + v1.y;
        acc.z += v0.z + v1.z;
        acc.w += v0.w + v1.w;
    }
    if (j < cnt) {
        int s0 = g_es[beg + j];
        float4 v0 = base[(size_t)s0 * 32 + lane];
        acc.x += v0.x; acc.y += v0.y; acc.z += v0.z; acc.w += v0.w;
    }

    float inv = g_inv[node];
    float4 o = make_float4(acc.x * inv, acc.y * inv, acc.z * inv, acc.w * inv);
    ((float4*)out)[(size_t)node * 32 + lane] = o;
}

// ---------------------------------------------------------------------------
extern "C" void kernel_launch(void* const* d_in, const int* in_sizes, int n_in,
                              void* d_out, int out_size) {
    const float* X = (const float*)d_in[0];
    const float* W = (const float*)d_in[1];
    const int* esrc = (const int*)d_in[2];
    const int* edst = (const int*)d_in[3];
    float* out = (float*)d_out;

    int n = in_sizes[0] / D;     // 50000
    int E = in_sizes[2];         // 800000

    static int smem_set = 0;
    int smem_bytes = D * D * sizeof(float) + BM * XS_LD * sizeof(float);
    if (!smem_set) {
        cudaFuncSetAttribute(k_gemm, cudaFuncAttributeMaxDynamicSharedMemorySize, smem_bytes);
        smem_set = 1;
    }

    k_zero<<<(n + 255) / 256, 256>>>(n);
    k_deg<<<(E + 255) / 256, 256>>>(edst, E);
    k_scan<<<1, SCAN_T>>>(n);
    k_fill<<<(E + 255) / 256, 256>>>(esrc, edst, E);
    k_gemm<<<(n + BM - 1) / BM, 256, smem_bytes>>>(X, W, n);

    int warps_per_block = 256 / 32;
    int nblk = (n + warps_per_block - 1) / warps_per_block;
    k_agg<<<nblk, 256>>>(out, n);
}